// round 15
// baseline (speedup 1.0000x reference)
#include <cuda_runtime.h>

#define T_LEN   16384
#define NUMB    64
#define KTAPS   129
#define TILE_T  128
#define BPB     8       // bands per block (1 per warp)
#define THREADS 256
#define NGROUPS (NUMB / BPB)
#define NTILES  (T_LEN / TILE_T)

// t-major partials: 8 floats (=2x float4) per t, one slot per band group
__device__ float4 g_part[T_LEN][2];
// per-tile arrival tickets; zero-init at load, reset by finalizer each launch
__device__ int g_cnt[NTILES];

__device__ __forceinline__ float ex2f(float x) {
    float r; asm("ex2.approx.ftz.f32 %0, %1;" : "=f"(r) : "f"(x)); return r;
}
__device__ __forceinline__ float sqrtaf(float x) {
    float r; asm("sqrt.approx.f32 %0, %1;" : "=f"(r) : "f"(x)); return r;
}

// Single-array conv pass for j=2,3 (window elems 2..7) fused with NC RBF
// centers [C0, C0+NC) for the j=0,1 outputs. One window + one weight vector
// live at a time -> low register pressure.
template<int C0, int NC>
__device__ __forceinline__ void conv_pass_rbf(
    const float4* __restrict__ x4, const float* __restrict__ wrow, int lane,
    float& acc0, float& acc1,
    const float4* __restrict__ qrow, const float2* __restrict__ w2row,
    const float* m01, const float* a01, float* oR01, float* oI01)
{
    float4 A = x4[lane];
    #pragma unroll
    for (int kg = 0; kg < 32; kg++) {
        float4 Bv = x4[lane + kg + 1];
        float4 w4 = *(const float4*)&wrow[4 * kg];
        float ax[6] = {A.z, A.w, Bv.x, Bv.y, Bv.z, Bv.w};
        float wv[4] = {w4.x, w4.y, w4.z, w4.w};
        #pragma unroll
        for (int kk = 0; kk < 4; kk++) {
            acc0 = fmaf(ax[kk],     wv[kk], acc0);
            acc1 = fmaf(ax[kk + 1], wv[kk], acc1);
        }
        if (kg < NC) {   // compile-time foldable (template bound)
            float4 q  = qrow[C0 + kg];
            float2 w2 = w2row[C0 + kg];
            #pragma unroll
            for (int j = 0; j < 2; j++) {
                float er = ex2f(fmaf(m01[j], q.x, a01[j] * q.y));
                oR01[j] = fmaf(er, w2.x, oR01[j]);
                float ei = ex2f(fmaf(m01[j], q.z, a01[j] * q.w));
                oI01[j] = fmaf(ei, w2.y, oI01[j]);
            }
        }
        A = Bv;
    }
    // tail tap k=128: x[4lane + (j+2) + 128] = x4[lane+32].{z,w}
    float wt = wrow[128];
    acc0 = fmaf(A.z, wt, acc0);
    acc1 = fmaf(A.w, wt, acc1);
}

__global__ __launch_bounds__(THREADS, 4)
void fused_kernel(const float* __restrict__ xr, const float* __restrict__ xi,
                  const float* __restrict__ w1r, const float* __restrict__ w1i,
                  const float* __restrict__ cr,  const float* __restrict__ ci,
                  const float* __restrict__ sr,  const float* __restrict__ si,
                  const float* __restrict__ fr,  const float* __restrict__ fi,
                  const float* __restrict__ w3r, const float* __restrict__ w3i,
                  float* __restrict__ out)
{
    // conv x-arrays and sred never live simultaneously -> union (sync-guarded)
    __shared__ __align__(16) union {
        struct { float r[TILE_T + 128]; float i[TILE_T + 128]; float s[TILE_T + 128]; } cx;
        float sred[BPB][TILE_T];
    } u;
    __shared__ __align__(16) float swr[BPB][132];   // wr
    __shared__ __align__(16) float swd[BPB][132];   // wi - wr
    __shared__ __align__(16) float sws[BPB][132];   // wi + wr
    __shared__ __align__(16) float4 sPq[BPB][NUMB]; // {pxr, pyr, pxi, pyi}
    __shared__ __align__(16) float2 sPw[BPB][NUMB]; // {fc_r*2^pzr, fc_i*2^pzi}
    __shared__ int s_ticket;

    const int tid  = threadIdx.x;
    const int wb   = tid >> 5;        // local band (warp)
    const int lane = tid & 31;
    const int tile = blockIdx.x;
    const int tileBase = tile * TILE_T;
    const int band = blockIdx.y * BPB + wb;

    // ---- stage x tile + halo (r, i, and s = r+i) ----
    for (int i = tid; i < TILE_T + 128; i += THREADS) {
        int t = tileBase - 64 + i;
        bool ok = (t >= 0) && (t < T_LEN);
        float vr = ok ? xr[t] : 0.0f;
        float vi = ok ? xi[t] : 0.0f;
        u.cx.r[i] = vr;
        u.cx.i[i] = vi;
        u.cx.s[i] = vr + vi;
    }
    // ---- stage Karatsuba weight triplets ----
    for (int i = tid; i < BPB * KTAPS; i += THREADS) {
        int bb = i / KTAPS, k = i - bb * KTAPS;
        int gb = blockIdx.y * BPB + bb;
        float wr = w1r[gb * KTAPS + k];
        float wi = w1i[gb * KTAPS + k];
        swr[bb][k] = wr;
        swd[bb][k] = wi - wr;
        sws[bb][k] = wi + wr;
    }
    // ---- inline RBF param precompute (2^pz folded into mixture weight) ----
    const float L = 1.4426950408889634f;  // log2(e)
    for (int i = tid; i < BPB * NUMB; i += THREADS) {
        int bb = i >> 6, c = i & 63;
        int idx = (blockIdx.y * BPB + bb) * NUMB + c;
        float s  = __ldg(&sr[idx]) * L;
        float cc = __ldg(&cr[idx]);
        float pxr = -s, pyr = 2.0f * s * cc;
        float pwr = __ldg(&fr[idx]) * ex2f(-s * cc * cc);
        s  = __ldg(&si[idx]) * L;
        cc = __ldg(&ci[idx]);
        float pxi = -s, pyi = 2.0f * s * cc;
        float pwi = __ldg(&fi[idx]) * ex2f(-s * cc * cc);
        sPq[bb][c] = make_float4(pxr, pyr, pxi, pyi);
        sPw[bb][c] = make_float2(pwr, pwi);
    }
    __syncthreads();

    const float4* xs4 = (const float4*)u.cx.s;
    const float4* xr4 = (const float4*)u.cx.r;
    const float4* xi4 = (const float4*)u.cx.i;
    const float4* qrow  = sPq[wb];
    const float2* w2row = sPw[wb];

    // ============================================================
    // PHASE A: Karatsuba conv for j = 0,1 (window elems 0..4)
    // ============================================================
    float A01[2] = {0.f,0.f}, B01[2] = {0.f,0.f}, C01[2] = {0.f,0.f};
    {
        float4 As = xs4[lane], Ar = xr4[lane], Ai = xi4[lane];
        #pragma unroll
        for (int kg = 0; kg < 32; kg++) {
            float4 Bs = xs4[lane + kg + 1];
            float4 Br = xr4[lane + kg + 1];
            float4 Bi = xi4[lane + kg + 1];
            float4 wr4 = *(const float4*)&swr[wb][4 * kg];
            float4 wd4 = *(const float4*)&swd[wb][4 * kg];
            float4 ws4 = *(const float4*)&sws[wb][4 * kg];
            float axs[5] = {As.x, As.y, As.z, As.w, Bs.x};
            float axr[5] = {Ar.x, Ar.y, Ar.z, Ar.w, Br.x};
            float axi[5] = {Ai.x, Ai.y, Ai.z, Ai.w, Bi.x};
            float wrv[4] = {wr4.x, wr4.y, wr4.z, wr4.w};
            float wdv[4] = {wd4.x, wd4.y, wd4.z, wd4.w};
            float wsv[4] = {ws4.x, ws4.y, ws4.z, ws4.w};
            #pragma unroll
            for (int kk = 0; kk < 4; kk++) {
                #pragma unroll
                for (int j = 0; j < 2; j++) {
                    A01[j] = fmaf(axs[kk + j], wrv[kk], A01[j]);
                    B01[j] = fmaf(axr[kk + j], wdv[kk], B01[j]);
                    C01[j] = fmaf(axi[kk + j], wsv[kk], C01[j]);
                }
            }
            As = Bs; Ar = Br; Ai = Bi;
        }
        // tail tap k = 128: x[4lane+j+128] = x4[lane+32].{x,y}
        float wr = swr[wb][128], wd = swd[wb][128], ws = sws[wb][128];
        #pragma unroll
        for (int j = 0; j < 2; j++) {
            float ts = (j == 0) ? As.x : As.y;
            float tr = (j == 0) ? Ar.x : Ar.y;
            float ti = (j == 0) ? Ai.x : Ai.y;
            A01[j] = fmaf(ts, wr, A01[j]);
            B01[j] = fmaf(tr, wd, B01[j]);
            C01[j] = fmaf(ti, ws, C01[j]);
        }
    }
    float x1r01[2], x1i01[2], m01[2], a01[2];
    #pragma unroll
    for (int j = 0; j < 2; j++) {
        x1r01[j] = A01[j] - C01[j];
        x1i01[j] = A01[j] + B01[j];
        m01[j] = x1r01[j] * x1r01[j] + x1i01[j] * x1i01[j];
        a01[j] = sqrtaf(m01[j]);
    }

    // =====================================================================
    // PHASE B: three single-array conv passes for j=2,3, each fused with a
    // slice of the j01 RBF centers (22 + 22 + 20 = 64).
    // =====================================================================
    float A23[2] = {0.f,0.f}, B23[2] = {0.f,0.f}, C23[2] = {0.f,0.f};
    float oR01[2] = {0.f,0.f}, oI01[2] = {0.f,0.f};
    conv_pass_rbf<0, 22>(xs4, swr[wb], lane, A23[0], A23[1],
                          qrow, w2row, m01, a01, oR01, oI01);
    conv_pass_rbf<22, 22>(xr4, swd[wb], lane, B23[0], B23[1],
                          qrow, w2row, m01, a01, oR01, oI01);
    conv_pass_rbf<44, 20>(xi4, sws[wb], lane, C23[0], C23[1],
                          qrow, w2row, m01, a01, oR01, oI01);

    float x1r23[2], x1i23[2], m23[2], a23[2];
    #pragma unroll
    for (int j = 0; j < 2; j++) {
        x1r23[j] = A23[j] - C23[j];
        x1i23[j] = A23[j] + B23[j];
        m23[j] = x1r23[j] * x1r23[j] + x1i23[j] * x1i23[j];
        a23[j] = sqrtaf(m23[j]);
    }

    // ============================================================
    // PHASE C: RBF for j = 2,3 (all 64 centers)
    // ============================================================
    float oR23[2] = {0.f,0.f}, oI23[2] = {0.f,0.f};
    #pragma unroll 4
    for (int c = 0; c < NUMB; c++) {
        float4 q  = qrow[c];
        float2 w2 = w2row[c];
        #pragma unroll
        for (int j = 0; j < 2; j++) {
            float er = ex2f(fmaf(m23[j], q.x, a23[j] * q.y));
            oR23[j] = fmaf(er, w2.x, oR23[j]);
            float ei = ex2f(fmaf(m23[j], q.z, a23[j] * q.w));
            oI23[j] = fmaf(ei, w2.y, oI23[j]);
        }
    }

    // ---- combine + band weight (real output only) ----
    float w3rb = __ldg(&w3r[band]);
    float w3ib = __ldg(&w3i[band]);
    float yv[4];
    #pragma unroll
    for (int j = 0; j < 2; j++) {
        float q   = oR01[j] + 1.0f;
        float x2r = q * x1r01[j] - oI01[j] * x1i01[j];
        float x2i = q * x1i01[j] + oI01[j] * x1r01[j];
        yv[j] = x2r * w3rb - x2i * w3ib;
        q   = oR23[j] + 1.0f;
        x2r = q * x1r23[j] - oI23[j] * x1i23[j];
        x2i = q * x1i23[j] + oI23[j] * x1r23[j];
        yv[j + 2] = x2r * w3rb - x2i * w3ib;
    }
    __syncthreads();   // all warps done reading u.cx before overlay reuse
    #pragma unroll
    for (int j = 0; j < 4; j++)
        u.sred[wb][4 * lane + j] = yv[j];
    __syncthreads();

    // ---- reduce 8 bands within block; publish t-major partial ----
    if (tid < TILE_T) {
        float r = 0.f;
        #pragma unroll
        for (int w = 0; w < BPB; w++) r += u.sred[w][tid];
        ((float*)&g_part[tileBase + tid][0])[blockIdx.y] = r;
    }

    // ---- fence + ticket: last block of this tile finalizes ----
    __threadfence();
    if (tid == 0)
        s_ticket = atomicAdd(&g_cnt[tile], 1);
    __syncthreads();
    if (s_ticket == NGROUPS - 1) {
        if (tid < TILE_T) {
            int t = tileBase + tid;
            float4 pa = g_part[t][0];
            float4 pb = g_part[t][1];
            out[t] = ((pa.x + pa.y) + (pa.z + pa.w)) + ((pb.x + pb.y) + (pb.z + pb.w));
        }
        if (tid == 0)
            g_cnt[tile] = 0;   // reset for next launch / graph replay
    }
}

extern "C" void kernel_launch(void* const* d_in, const int* in_sizes, int n_in,
                              void* d_out, int out_size)
{
    // Input ordering: order A (dict/signature) confirmed (in_sizes[0]==16384).
    int I_xr, I_xi, I_w1r, I_w1i, I_cr, I_ci, I_sr, I_si, I_fcr, I_fci, I_w3r, I_w3i;
    if (in_sizes[0] == T_LEN) {
        I_xr = 0;  I_xi = 1;  I_w1r = 2; I_w1i = 3; I_cr = 4;  I_ci = 5;
        I_sr = 6;  I_si = 7;  I_fcr = 8; I_fci = 9; I_w3r = 10; I_w3i = 11;
    } else {
        I_ci = 0;  I_cr = 1;  I_fci = 2; I_fcr = 3; I_si = 4;  I_sr = 5;
        I_w1i = 6; I_w1r = 7; I_w3i = 8; I_w3r = 9; I_xi = 10; I_xr = 11;
    }

    const float* x_r  = (const float*)d_in[I_xr];
    const float* x_i  = (const float*)d_in[I_xi];
    const float* w1_r = (const float*)d_in[I_w1r];
    const float* w1_i = (const float*)d_in[I_w1i];
    const float* c_r  = (const float*)d_in[I_cr];
    const float* c_i  = (const float*)d_in[I_ci];
    const float* s_r  = (const float*)d_in[I_sr];
    const float* s_i  = (const float*)d_in[I_si];
    const float* fc_r = (const float*)d_in[I_fcr];
    const float* fc_i = (const float*)d_in[I_fci];
    const float* w3_r = (const float*)d_in[I_w3r];
    const float* w3_i = (const float*)d_in[I_w3i];
    float* out = (float*)d_out;

    dim3 grid(NTILES, NGROUPS);
    fused_kernel<<<grid, THREADS>>>(x_r, x_i, w1_r, w1_i,
                                    c_r, c_i, s_r, s_i, fc_r, fc_i,
                                    w3_r, w3_i, out);
}

// round 16
// speedup vs baseline: 1.0192x; 1.0192x over previous
#include <cuda_runtime.h>

#define T_LEN   16384
#define NUMB    64
#define KTAPS   129
#define TILE_T  128
#define BPB     8       // bands per block (1 per warp)
#define THREADS 256
#define NGROUPS (NUMB / BPB)
#define NTILES  (T_LEN / TILE_T)

// t-major partials: 8 floats (=2x float4) per t, one slot per band group
__device__ float4 g_part[T_LEN][2];
// per-tile arrival tickets; zero-init at load, reset by finalizer each launch
__device__ int g_cnt[NTILES];

__device__ __forceinline__ float ex2f(float x) {
    float r; asm("ex2.approx.ftz.f32 %0, %1;" : "=f"(r) : "f"(x)); return r;
}
__device__ __forceinline__ float sqrtaf(float x) {
    float r; asm("sqrt.approx.f32 %0, %1;" : "=f"(r) : "f"(x)); return r;
}

__global__ __launch_bounds__(THREADS, 4)
void fused_kernel(const float* __restrict__ xr, const float* __restrict__ xi,
                  const float* __restrict__ w1r, const float* __restrict__ w1i,
                  const float* __restrict__ cr,  const float* __restrict__ ci,
                  const float* __restrict__ sr,  const float* __restrict__ si,
                  const float* __restrict__ fr,  const float* __restrict__ fi,
                  const float* __restrict__ w3r, const float* __restrict__ w3i,
                  float* __restrict__ out)
{
    // conv x-arrays and sred never live simultaneously -> union (sync-guarded)
    __shared__ __align__(16) union {
        struct { float r[TILE_T + 128]; float i[TILE_T + 128]; float s[TILE_T + 128]; } cx;
        float sred[BPB][TILE_T];
    } u;
    __shared__ __align__(16) float swr[BPB][132];   // wr
    __shared__ __align__(16) float swd[BPB][132];   // wi - wr
    __shared__ __align__(16) float sws[BPB][132];   // wi + wr
    __shared__ __align__(16) float4 sPq[BPB][NUMB]; // {pxr, pyr, pxi, pyi}
    __shared__ __align__(16) float2 sPw[BPB][NUMB]; // {fc_r*2^pzr, fc_i*2^pzi}
    __shared__ int s_ticket;

    const int tid  = threadIdx.x;
    const int wb   = tid >> 5;        // local band (warp)
    const int lane = tid & 31;
    const int tile = blockIdx.x;
    const int tileBase = tile * TILE_T;
    const int band = blockIdx.y * BPB + wb;

    // ---- stage x tile + halo (r, i, and s = r+i) ----
    for (int i = tid; i < TILE_T + 128; i += THREADS) {
        int t = tileBase - 64 + i;
        bool ok = (t >= 0) && (t < T_LEN);
        float vr = ok ? xr[t] : 0.0f;
        float vi = ok ? xi[t] : 0.0f;
        u.cx.r[i] = vr;
        u.cx.i[i] = vi;
        u.cx.s[i] = vr + vi;
    }
    // ---- stage Karatsuba weight triplets ----
    for (int i = tid; i < BPB * KTAPS; i += THREADS) {
        int bb = i / KTAPS, k = i - bb * KTAPS;
        int gb = blockIdx.y * BPB + bb;
        float wr = w1r[gb * KTAPS + k];
        float wi = w1i[gb * KTAPS + k];
        swr[bb][k] = wr;
        swd[bb][k] = wi - wr;
        sws[bb][k] = wi + wr;
    }
    // ---- inline RBF param precompute (2^pz folded into mixture weight) ----
    const float L = 1.4426950408889634f;  // log2(e)
    for (int i = tid; i < BPB * NUMB; i += THREADS) {
        int bb = i >> 6, c = i & 63;
        int idx = (blockIdx.y * BPB + bb) * NUMB + c;
        float s  = __ldg(&sr[idx]) * L;
        float cc = __ldg(&cr[idx]);
        float pxr = -s, pyr = 2.0f * s * cc;
        float pwr = __ldg(&fr[idx]) * ex2f(-s * cc * cc);
        s  = __ldg(&si[idx]) * L;
        cc = __ldg(&ci[idx]);
        float pxi = -s, pyi = 2.0f * s * cc;
        float pwi = __ldg(&fi[idx]) * ex2f(-s * cc * cc);
        sPq[bb][c] = make_float4(pxr, pyr, pxi, pyi);
        sPw[bb][c] = make_float2(pwr, pwi);
    }
    __syncthreads();

    const float4* xs4 = (const float4*)u.cx.s;
    const float4* xr4 = (const float4*)u.cx.r;
    const float4* xi4 = (const float4*)u.cx.i;
    const float4* qrow  = sPq[wb];
    const float2* w2row = sPw[wb];

    // ============================================================
    // PHASE A: Karatsuba conv for j = 0,1 (window elems 0..4)
    // ============================================================
    float cA0 = 0.f, cA1 = 0.f, cB0 = 0.f, cB1 = 0.f, cC0 = 0.f, cC1 = 0.f;
    {
        float4 As = xs4[lane], Ar = xr4[lane], Ai = xi4[lane];
        #pragma unroll
        for (int kg = 0; kg < 32; kg++) {
            float4 Bs = xs4[lane + kg + 1];
            float4 Br = xr4[lane + kg + 1];
            float4 Bi = xi4[lane + kg + 1];
            float4 wr4 = *(const float4*)&swr[wb][4 * kg];
            float4 wd4 = *(const float4*)&swd[wb][4 * kg];
            float4 ws4 = *(const float4*)&sws[wb][4 * kg];
            float axs[5] = {As.x, As.y, As.z, As.w, Bs.x};
            float axr[5] = {Ar.x, Ar.y, Ar.z, Ar.w, Br.x};
            float axi[5] = {Ai.x, Ai.y, Ai.z, Ai.w, Bi.x};
            float wrv[4] = {wr4.x, wr4.y, wr4.z, wr4.w};
            float wdv[4] = {wd4.x, wd4.y, wd4.z, wd4.w};
            float wsv[4] = {ws4.x, ws4.y, ws4.z, ws4.w};
            #pragma unroll
            for (int kk = 0; kk < 4; kk++) {
                cA0 = fmaf(axs[kk],     wrv[kk], cA0);
                cA1 = fmaf(axs[kk + 1], wrv[kk], cA1);
                cB0 = fmaf(axr[kk],     wdv[kk], cB0);
                cB1 = fmaf(axr[kk + 1], wdv[kk], cB1);
                cC0 = fmaf(axi[kk],     wsv[kk], cC0);
                cC1 = fmaf(axi[kk + 1], wsv[kk], cC1);
            }
            As = Bs; Ar = Br; Ai = Bi;
        }
        // tail tap k = 128: x[4lane+j+128] = carried word .x/.y
        float wr = swr[wb][128], wd = swd[wb][128], ws = sws[wb][128];
        cA0 = fmaf(As.x, wr, cA0);  cA1 = fmaf(As.y, wr, cA1);
        cB0 = fmaf(Ar.x, wd, cB0);  cB1 = fmaf(Ar.y, wd, cB1);
        cC0 = fmaf(Ai.x, ws, cC0);  cC1 = fmaf(Ai.y, ws, cC1);
    }
    const float x1r0 = cA0 - cC0, x1r1 = cA1 - cC1;
    const float x1i0 = cA0 + cB0, x1i1 = cA1 + cB1;
    const float m0 = x1r0 * x1r0 + x1i0 * x1i0;
    const float m1 = x1r1 * x1r1 + x1i1 * x1i1;
    const float a0 = sqrtaf(m0);
    const float a1 = sqrtaf(m1);

    // =====================================================================
    // PHASE B: three single-stream conv passes for j=2,3 (window elems 2..6)
    // each fused with a slice of the j01 RBF centers (22+22+20 = 64).
    // Fully scalar: no arrays, no pointer-passed state.
    // =====================================================================
    float oR0 = 0.f, oR1 = 0.f, oI0 = 0.f, oI1 = 0.f;
    float aS0 = 0.f, aS1 = 0.f, aR0 = 0.f, aR1 = 0.f, aI0 = 0.f, aI1 = 0.f;

    {   // pass 1: stream s, weights wr, centers 0..21
        const float* wrow = swr[wb];
        float4 A = xs4[lane];
        float p0 = A.z, p1 = A.w;
        #pragma unroll
        for (int kg = 0; kg < 32; kg++) {
            float4 Bv = xs4[lane + kg + 1];
            float4 w4 = *(const float4*)&wrow[4 * kg];
            aS0 = fmaf(p0,   w4.x, aS0);  aS1 = fmaf(p1,   w4.x, aS1);
            aS0 = fmaf(p1,   w4.y, aS0);  aS1 = fmaf(Bv.x, w4.y, aS1);
            aS0 = fmaf(Bv.x, w4.z, aS0);  aS1 = fmaf(Bv.y, w4.z, aS1);
            aS0 = fmaf(Bv.y, w4.w, aS0);  aS1 = fmaf(Bv.z, w4.w, aS1);
            if (kg < 22) {
                float4 q  = qrow[kg];
                float2 ww = w2row[kg];
                float e;
                e = ex2f(fmaf(m0, q.x, a0 * q.y)); oR0 = fmaf(e, ww.x, oR0);
                e = ex2f(fmaf(m1, q.x, a1 * q.y)); oR1 = fmaf(e, ww.x, oR1);
                e = ex2f(fmaf(m0, q.z, a0 * q.w)); oI0 = fmaf(e, ww.y, oI0);
                e = ex2f(fmaf(m1, q.z, a1 * q.w)); oI1 = fmaf(e, ww.y, oI1);
            }
            p0 = Bv.z; p1 = Bv.w;
        }
        float wt = wrow[128];
        aS0 = fmaf(p0, wt, aS0);  aS1 = fmaf(p1, wt, aS1);
    }
    {   // pass 2: stream r, weights wd, centers 22..43
        const float* wrow = swd[wb];
        float4 A = xr4[lane];
        float p0 = A.z, p1 = A.w;
        #pragma unroll
        for (int kg = 0; kg < 32; kg++) {
            float4 Bv = xr4[lane + kg + 1];
            float4 w4 = *(const float4*)&wrow[4 * kg];
            aR0 = fmaf(p0,   w4.x, aR0);  aR1 = fmaf(p1,   w4.x, aR1);
            aR0 = fmaf(p1,   w4.y, aR0);  aR1 = fmaf(Bv.x, w4.y, aR1);
            aR0 = fmaf(Bv.x, w4.z, aR0);  aR1 = fmaf(Bv.y, w4.z, aR1);
            aR0 = fmaf(Bv.y, w4.w, aR0);  aR1 = fmaf(Bv.z, w4.w, aR1);
            if (kg < 22) {
                float4 q  = qrow[22 + kg];
                float2 ww = w2row[22 + kg];
                float e;
                e = ex2f(fmaf(m0, q.x, a0 * q.y)); oR0 = fmaf(e, ww.x, oR0);
                e = ex2f(fmaf(m1, q.x, a1 * q.y)); oR1 = fmaf(e, ww.x, oR1);
                e = ex2f(fmaf(m0, q.z, a0 * q.w)); oI0 = fmaf(e, ww.y, oI0);
                e = ex2f(fmaf(m1, q.z, a1 * q.w)); oI1 = fmaf(e, ww.y, oI1);
            }
            p0 = Bv.z; p1 = Bv.w;
        }
        float wt = wrow[128];
        aR0 = fmaf(p0, wt, aR0);  aR1 = fmaf(p1, wt, aR1);
    }
    {   // pass 3: stream i, weights ws, centers 44..63
        const float* wrow = sws[wb];
        float4 A = xi4[lane];
        float p0 = A.z, p1 = A.w;
        #pragma unroll
        for (int kg = 0; kg < 32; kg++) {
            float4 Bv = xi4[lane + kg + 1];
            float4 w4 = *(const float4*)&wrow[4 * kg];
            aI0 = fmaf(p0,   w4.x, aI0);  aI1 = fmaf(p1,   w4.x, aI1);
            aI0 = fmaf(p1,   w4.y, aI0);  aI1 = fmaf(Bv.x, w4.y, aI1);
            aI0 = fmaf(Bv.x, w4.z, aI0);  aI1 = fmaf(Bv.y, w4.z, aI1);
            aI0 = fmaf(Bv.y, w4.w, aI0);  aI1 = fmaf(Bv.z, w4.w, aI1);
            if (kg < 20) {
                float4 q  = qrow[44 + kg];
                float2 ww = w2row[44 + kg];
                float e;
                e = ex2f(fmaf(m0, q.x, a0 * q.y)); oR0 = fmaf(e, ww.x, oR0);
                e = ex2f(fmaf(m1, q.x, a1 * q.y)); oR1 = fmaf(e, ww.x, oR1);
                e = ex2f(fmaf(m0, q.z, a0 * q.w)); oI0 = fmaf(e, ww.y, oI0);
                e = ex2f(fmaf(m1, q.z, a1 * q.w)); oI1 = fmaf(e, ww.y, oI1);
            }
            p0 = Bv.z; p1 = Bv.w;
        }
        float wt = wrow[128];
        aI0 = fmaf(p0, wt, aI0);  aI1 = fmaf(p1, wt, aI1);
    }

    const float x1r2 = aS0 - aI0, x1r3 = aS1 - aI1;
    const float x1i2 = aS0 + aR0, x1i3 = aS1 + aR1;
    const float m2 = x1r2 * x1r2 + x1i2 * x1i2;
    const float m3 = x1r3 * x1r3 + x1i3 * x1i3;
    const float a2 = sqrtaf(m2);
    const float a3 = sqrtaf(m3);

    // ============================================================
    // PHASE C: RBF for j = 2,3 (all 64 centers), scalar
    // ============================================================
    float oR2 = 0.f, oR3 = 0.f, oI2 = 0.f, oI3 = 0.f;
    #pragma unroll 4
    for (int c = 0; c < NUMB; c++) {
        float4 q  = qrow[c];
        float2 ww = w2row[c];
        float e;
        e = ex2f(fmaf(m2, q.x, a2 * q.y)); oR2 = fmaf(e, ww.x, oR2);
        e = ex2f(fmaf(m3, q.x, a3 * q.y)); oR3 = fmaf(e, ww.x, oR3);
        e = ex2f(fmaf(m2, q.z, a2 * q.w)); oI2 = fmaf(e, ww.y, oI2);
        e = ex2f(fmaf(m3, q.z, a3 * q.w)); oI3 = fmaf(e, ww.y, oI3);
    }

    // ---- combine + band weight (real output only) ----
    float w3rb = __ldg(&w3r[band]);
    float w3ib = __ldg(&w3i[band]);
    float y0, y1, y2, y3;
    {
        float q, x2r, x2i;
        q = oR0 + 1.0f; x2r = q * x1r0 - oI0 * x1i0; x2i = q * x1i0 + oI0 * x1r0;
        y0 = x2r * w3rb - x2i * w3ib;
        q = oR1 + 1.0f; x2r = q * x1r1 - oI1 * x1i1; x2i = q * x1i1 + oI1 * x1r1;
        y1 = x2r * w3rb - x2i * w3ib;
        q = oR2 + 1.0f; x2r = q * x1r2 - oI2 * x1i2; x2i = q * x1i2 + oI2 * x1r2;
        y2 = x2r * w3rb - x2i * w3ib;
        q = oR3 + 1.0f; x2r = q * x1r3 - oI3 * x1i3; x2i = q * x1i3 + oI3 * x1r3;
        y3 = x2r * w3rb - x2i * w3ib;
    }
    __syncthreads();   // all warps done reading u.cx before overlay reuse
    u.sred[wb][4 * lane + 0] = y0;
    u.sred[wb][4 * lane + 1] = y1;
    u.sred[wb][4 * lane + 2] = y2;
    u.sred[wb][4 * lane + 3] = y3;
    __syncthreads();

    // ---- reduce 8 bands within block; publish t-major partial ----
    if (tid < TILE_T) {
        float r = 0.f;
        #pragma unroll
        for (int w = 0; w < BPB; w++) r += u.sred[w][tid];
        ((float*)&g_part[tileBase + tid][0])[blockIdx.y] = r;
    }

    // ---- fence + ticket: last block of this tile finalizes ----
    __threadfence();
    if (tid == 0)
        s_ticket = atomicAdd(&g_cnt[tile], 1);
    __syncthreads();
    if (s_ticket == NGROUPS - 1) {
        if (tid < TILE_T) {
            int t = tileBase + tid;
            float4 pa = g_part[t][0];
            float4 pb = g_part[t][1];
            out[t] = ((pa.x + pa.y) + (pa.z + pa.w)) + ((pb.x + pb.y) + (pb.z + pb.w));
        }
        if (tid == 0)
            g_cnt[tile] = 0;   // reset for next launch / graph replay
    }
}

extern "C" void kernel_launch(void* const* d_in, const int* in_sizes, int n_in,
                              void* d_out, int out_size)
{
    // Input ordering: order A (dict/signature) confirmed (in_sizes[0]==16384).
    int I_xr, I_xi, I_w1r, I_w1i, I_cr, I_ci, I_sr, I_si, I_fcr, I_fci, I_w3r, I_w3i;
    if (in_sizes[0] == T_LEN) {
        I_xr = 0;  I_xi = 1;  I_w1r = 2; I_w1i = 3; I_cr = 4;  I_ci = 5;
        I_sr = 6;  I_si = 7;  I_fcr = 8; I_fci = 9; I_w3r = 10; I_w3i = 11;
    } else {
        I_ci = 0;  I_cr = 1;  I_fci = 2; I_fcr = 3; I_si = 4;  I_sr = 5;
        I_w1i = 6; I_w1r = 7; I_w3i = 8; I_w3r = 9; I_xi = 10; I_xr = 11;
    }

    const float* x_r  = (const float*)d_in[I_xr];
    const float* x_i  = (const float*)d_in[I_xi];
    const float* w1_r = (const float*)d_in[I_w1r];
    const float* w1_i = (const float*)d_in[I_w1i];
    const float* c_r  = (const float*)d_in[I_cr];
    const float* c_i  = (const float*)d_in[I_ci];
    const float* s_r  = (const float*)d_in[I_sr];
    const float* s_i  = (const float*)d_in[I_si];
    const float* fc_r = (const float*)d_in[I_fcr];
    const float* fc_i = (const float*)d_in[I_fci];
    const float* w3_r = (const float*)d_in[I_w3r];
    const float* w3_i = (const float*)d_in[I_w3i];
    float* out = (float*)d_out;

    dim3 grid(NTILES, NGROUPS);
    fused_kernel<<<grid, THREADS>>>(x_r, x_i, w1_r, w1_i,
                                    c_r, c_i, s_r, s_i, fc_r, fc_i,
                                    w3_r, w3_i, out);
}

// round 17
// speedup vs baseline: 1.1279x; 1.1067x over previous
#include <cuda_runtime.h>

#define T_LEN   16384
#define NUMB    64
#define KTAPS   129
#define TILE_T  128
#define BPB     8       // bands per block (1 per warp)
#define THREADS 256
#define NGROUPS (NUMB / BPB)
#define NTILES  (T_LEN / TILE_T)

// t-major partials: 8 floats (=2x float4) per t, one slot per band group
__device__ float4 g_part[T_LEN][2];
// per-tile arrival tickets; zero-init at load, reset by finalizer each launch
__device__ int g_cnt[NTILES];

__device__ __forceinline__ float ex2f(float x) {
    float r; asm("ex2.approx.ftz.f32 %0, %1;" : "=f"(r) : "f"(x)); return r;
}
__device__ __forceinline__ float sqrtaf(float x) {
    float r; asm("sqrt.approx.f32 %0, %1;" : "=f"(r) : "f"(x)); return r;
}

__global__ __launch_bounds__(THREADS, 3)
void fused_kernel(const float* __restrict__ xr, const float* __restrict__ xi,
                  const float* __restrict__ w1r, const float* __restrict__ w1i,
                  const float* __restrict__ cr,  const float* __restrict__ ci,
                  const float* __restrict__ sr,  const float* __restrict__ si,
                  const float* __restrict__ fr,  const float* __restrict__ fi,
                  const float* __restrict__ w3r, const float* __restrict__ w3i,
                  float* __restrict__ out)
{
    // conv x-arrays and sred never live simultaneously -> union (sync-guarded)
    __shared__ __align__(16) union {
        struct { float r[TILE_T + 128]; float i[TILE_T + 128]; float s[TILE_T + 128]; } cx;
        float sred[BPB][TILE_T];
    } u;
    __shared__ __align__(16) float swr[BPB][132];   // wr
    __shared__ __align__(16) float swd[BPB][132];   // wi - wr
    __shared__ __align__(16) float sws[BPB][132];   // wi + wr
    __shared__ __align__(16) float4 sPq[BPB][NUMB]; // {pxr, pyr, pxi, pyi}
    __shared__ __align__(16) float2 sPw[BPB][NUMB]; // {fc_r*2^pzr, fc_i*2^pzi}
    __shared__ int s_ticket;

    const int tid  = threadIdx.x;
    const int wb   = tid >> 5;        // local band (warp)
    const int lane = tid & 31;
    const int tile = blockIdx.x;
    const int tileBase = tile * TILE_T;
    const int band = blockIdx.y * BPB + wb;

    // ---- stage x tile + halo (r, i, and s = r+i) ----
    for (int i = tid; i < TILE_T + 128; i += THREADS) {
        int t = tileBase - 64 + i;
        bool ok = (t >= 0) && (t < T_LEN);
        float vr = ok ? xr[t] : 0.0f;
        float vi = ok ? xi[t] : 0.0f;
        u.cx.r[i] = vr;
        u.cx.i[i] = vi;
        u.cx.s[i] = vr + vi;
    }
    // ---- stage Karatsuba weight triplets ----
    for (int i = tid; i < BPB * KTAPS; i += THREADS) {
        int bb = i / KTAPS, k = i - bb * KTAPS;
        int gb = blockIdx.y * BPB + bb;
        float wr = w1r[gb * KTAPS + k];
        float wi = w1i[gb * KTAPS + k];
        swr[bb][k] = wr;
        swd[bb][k] = wi - wr;
        sws[bb][k] = wi + wr;
    }
    // ---- inline RBF param precompute (2^pz folded into mixture weight) ----
    const float L = 1.4426950408889634f;  // log2(e)
    for (int i = tid; i < BPB * NUMB; i += THREADS) {
        int bb = i >> 6, c = i & 63;
        int idx = (blockIdx.y * BPB + bb) * NUMB + c;
        float s  = __ldg(&sr[idx]) * L;
        float cc = __ldg(&cr[idx]);
        float pxr = -s, pyr = 2.0f * s * cc;
        float pwr = __ldg(&fr[idx]) * ex2f(-s * cc * cc);
        s  = __ldg(&si[idx]) * L;
        cc = __ldg(&ci[idx]);
        float pxi = -s, pyi = 2.0f * s * cc;
        float pwi = __ldg(&fi[idx]) * ex2f(-s * cc * cc);
        sPq[bb][c] = make_float4(pxr, pyr, pxi, pyi);
        sPw[bb][c] = make_float2(pwr, pwi);
    }
    __syncthreads();

    const float4* xs4 = (const float4*)u.cx.s;
    const float4* xr4 = (const float4*)u.cx.r;
    const float4* xi4 = (const float4*)u.cx.i;
    const float4* qrow  = sPq[wb];
    const float2* w2row = sPw[wb];

    // ============================================================
    // PHASE A: Karatsuba conv for j = 0,1 (window elems 0..4)
    // ============================================================
    float cA0 = 0.f, cA1 = 0.f, cB0 = 0.f, cB1 = 0.f, cC0 = 0.f, cC1 = 0.f;
    {
        float4 As = xs4[lane], Ar = xr4[lane], Ai = xi4[lane];
        #pragma unroll
        for (int kg = 0; kg < 32; kg++) {
            float4 Bs = xs4[lane + kg + 1];
            float4 Br = xr4[lane + kg + 1];
            float4 Bi = xi4[lane + kg + 1];
            float4 wr4 = *(const float4*)&swr[wb][4 * kg];
            float4 wd4 = *(const float4*)&swd[wb][4 * kg];
            float4 ws4 = *(const float4*)&sws[wb][4 * kg];
            float axs[5] = {As.x, As.y, As.z, As.w, Bs.x};
            float axr[5] = {Ar.x, Ar.y, Ar.z, Ar.w, Br.x};
            float axi[5] = {Ai.x, Ai.y, Ai.z, Ai.w, Bi.x};
            float wrv[4] = {wr4.x, wr4.y, wr4.z, wr4.w};
            float wdv[4] = {wd4.x, wd4.y, wd4.z, wd4.w};
            float wsv[4] = {ws4.x, ws4.y, ws4.z, ws4.w};
            #pragma unroll
            for (int kk = 0; kk < 4; kk++) {
                cA0 = fmaf(axs[kk],     wrv[kk], cA0);
                cA1 = fmaf(axs[kk + 1], wrv[kk], cA1);
                cB0 = fmaf(axr[kk],     wdv[kk], cB0);
                cB1 = fmaf(axr[kk + 1], wdv[kk], cB1);
                cC0 = fmaf(axi[kk],     wsv[kk], cC0);
                cC1 = fmaf(axi[kk + 1], wsv[kk], cC1);
            }
            As = Bs; Ar = Br; Ai = Bi;
        }
        // tail tap k = 128: x[4lane+j+128] = carried word .x/.y
        float wr = swr[wb][128], wd = swd[wb][128], ws = sws[wb][128];
        cA0 = fmaf(As.x, wr, cA0);  cA1 = fmaf(As.y, wr, cA1);
        cB0 = fmaf(Ar.x, wd, cB0);  cB1 = fmaf(Ar.y, wd, cB1);
        cC0 = fmaf(Ai.x, ws, cC0);  cC1 = fmaf(Ai.y, ws, cC1);
    }
    const float x1r0 = cA0 - cC0, x1r1 = cA1 - cC1;
    const float x1i0 = cA0 + cB0, x1i1 = cA1 + cB1;
    const float m0 = x1r0 * x1r0 + x1i0 * x1i0;
    const float m1 = x1r1 * x1r1 + x1i1 * x1i1;
    const float a0 = sqrtaf(m0);
    const float a1 = sqrtaf(m1);

    // =====================================================================
    // PHASE B: three single-stream conv passes for j=2,3 (window elems 2..6)
    // each fused with a slice of the j01 RBF centers (22+22+20 = 64).
    // Fully scalar: no arrays, no pointer-passed state.
    // =====================================================================
    float oR0 = 0.f, oR1 = 0.f, oI0 = 0.f, oI1 = 0.f;
    float aS0 = 0.f, aS1 = 0.f, aR0 = 0.f, aR1 = 0.f, aI0 = 0.f, aI1 = 0.f;

    {   // pass 1: stream s, weights wr, centers 0..21
        const float* wrow = swr[wb];
        float4 A = xs4[lane];
        float p0 = A.z, p1 = A.w;
        #pragma unroll
        for (int kg = 0; kg < 32; kg++) {
            float4 Bv = xs4[lane + kg + 1];
            float4 w4 = *(const float4*)&wrow[4 * kg];
            aS0 = fmaf(p0,   w4.x, aS0);  aS1 = fmaf(p1,   w4.x, aS1);
            aS0 = fmaf(p1,   w4.y, aS0);  aS1 = fmaf(Bv.x, w4.y, aS1);
            aS0 = fmaf(Bv.x, w4.z, aS0);  aS1 = fmaf(Bv.y, w4.z, aS1);
            aS0 = fmaf(Bv.y, w4.w, aS0);  aS1 = fmaf(Bv.z, w4.w, aS1);
            if (kg < 22) {
                float4 q  = qrow[kg];
                float2 ww = w2row[kg];
                float e;
                e = ex2f(fmaf(m0, q.x, a0 * q.y)); oR0 = fmaf(e, ww.x, oR0);
                e = ex2f(fmaf(m1, q.x, a1 * q.y)); oR1 = fmaf(e, ww.x, oR1);
                e = ex2f(fmaf(m0, q.z, a0 * q.w)); oI0 = fmaf(e, ww.y, oI0);
                e = ex2f(fmaf(m1, q.z, a1 * q.w)); oI1 = fmaf(e, ww.y, oI1);
            }
            p0 = Bv.z; p1 = Bv.w;
        }
        float wt = wrow[128];
        aS0 = fmaf(p0, wt, aS0);  aS1 = fmaf(p1, wt, aS1);
    }
    {   // pass 2: stream r, weights wd, centers 22..43
        const float* wrow = swd[wb];
        float4 A = xr4[lane];
        float p0 = A.z, p1 = A.w;
        #pragma unroll
        for (int kg = 0; kg < 32; kg++) {
            float4 Bv = xr4[lane + kg + 1];
            float4 w4 = *(const float4*)&wrow[4 * kg];
            aR0 = fmaf(p0,   w4.x, aR0);  aR1 = fmaf(p1,   w4.x, aR1);
            aR0 = fmaf(p1,   w4.y, aR0);  aR1 = fmaf(Bv.x, w4.y, aR1);
            aR0 = fmaf(Bv.x, w4.z, aR0);  aR1 = fmaf(Bv.y, w4.z, aR1);
            aR0 = fmaf(Bv.y, w4.w, aR0);  aR1 = fmaf(Bv.z, w4.w, aR1);
            if (kg < 22) {
                float4 q  = qrow[22 + kg];
                float2 ww = w2row[22 + kg];
                float e;
                e = ex2f(fmaf(m0, q.x, a0 * q.y)); oR0 = fmaf(e, ww.x, oR0);
                e = ex2f(fmaf(m1, q.x, a1 * q.y)); oR1 = fmaf(e, ww.x, oR1);
                e = ex2f(fmaf(m0, q.z, a0 * q.w)); oI0 = fmaf(e, ww.y, oI0);
                e = ex2f(fmaf(m1, q.z, a1 * q.w)); oI1 = fmaf(e, ww.y, oI1);
            }
            p0 = Bv.z; p1 = Bv.w;
        }
        float wt = wrow[128];
        aR0 = fmaf(p0, wt, aR0);  aR1 = fmaf(p1, wt, aR1);
    }
    {   // pass 3: stream i, weights ws, centers 44..63
        const float* wrow = sws[wb];
        float4 A = xi4[lane];
        float p0 = A.z, p1 = A.w;
        #pragma unroll
        for (int kg = 0; kg < 32; kg++) {
            float4 Bv = xi4[lane + kg + 1];
            float4 w4 = *(const float4*)&wrow[4 * kg];
            aI0 = fmaf(p0,   w4.x, aI0);  aI1 = fmaf(p1,   w4.x, aI1);
            aI0 = fmaf(p1,   w4.y, aI0);  aI1 = fmaf(Bv.x, w4.y, aI1);
            aI0 = fmaf(Bv.x, w4.z, aI0);  aI1 = fmaf(Bv.y, w4.z, aI1);
            aI0 = fmaf(Bv.y, w4.w, aI0);  aI1 = fmaf(Bv.z, w4.w, aI1);
            if (kg < 20) {
                float4 q  = qrow[44 + kg];
                float2 ww = w2row[44 + kg];
                float e;
                e = ex2f(fmaf(m0, q.x, a0 * q.y)); oR0 = fmaf(e, ww.x, oR0);
                e = ex2f(fmaf(m1, q.x, a1 * q.y)); oR1 = fmaf(e, ww.x, oR1);
                e = ex2f(fmaf(m0, q.z, a0 * q.w)); oI0 = fmaf(e, ww.y, oI0);
                e = ex2f(fmaf(m1, q.z, a1 * q.w)); oI1 = fmaf(e, ww.y, oI1);
            }
            p0 = Bv.z; p1 = Bv.w;
        }
        float wt = wrow[128];
        aI0 = fmaf(p0, wt, aI0);  aI1 = fmaf(p1, wt, aI1);
    }

    const float x1r2 = aS0 - aI0, x1r3 = aS1 - aI1;
    const float x1i2 = aS0 + aR0, x1i3 = aS1 + aR1;
    const float m2 = x1r2 * x1r2 + x1i2 * x1i2;
    const float m3 = x1r3 * x1r3 + x1i3 * x1i3;
    const float a2 = sqrtaf(m2);
    const float a3 = sqrtaf(m3);

    // ============================================================
    // PHASE C: RBF for j = 2,3 (all 64 centers), scalar
    // ============================================================
    float oR2 = 0.f, oR3 = 0.f, oI2 = 0.f, oI3 = 0.f;
    #pragma unroll 4
    for (int c = 0; c < NUMB; c++) {
        float4 q  = qrow[c];
        float2 ww = w2row[c];
        float e;
        e = ex2f(fmaf(m2, q.x, a2 * q.y)); oR2 = fmaf(e, ww.x, oR2);
        e = ex2f(fmaf(m3, q.x, a3 * q.y)); oR3 = fmaf(e, ww.x, oR3);
        e = ex2f(fmaf(m2, q.z, a2 * q.w)); oI2 = fmaf(e, ww.y, oI2);
        e = ex2f(fmaf(m3, q.z, a3 * q.w)); oI3 = fmaf(e, ww.y, oI3);
    }

    // ---- combine + band weight (real output only) ----
    float w3rb = __ldg(&w3r[band]);
    float w3ib = __ldg(&w3i[band]);
    float y0, y1, y2, y3;
    {
        float q, x2r, x2i;
        q = oR0 + 1.0f; x2r = q * x1r0 - oI0 * x1i0; x2i = q * x1i0 + oI0 * x1r0;
        y0 = x2r * w3rb - x2i * w3ib;
        q = oR1 + 1.0f; x2r = q * x1r1 - oI1 * x1i1; x2i = q * x1i1 + oI1 * x1r1;
        y1 = x2r * w3rb - x2i * w3ib;
        q = oR2 + 1.0f; x2r = q * x1r2 - oI2 * x1i2; x2i = q * x1i2 + oI2 * x1r2;
        y2 = x2r * w3rb - x2i * w3ib;
        q = oR3 + 1.0f; x2r = q * x1r3 - oI3 * x1i3; x2i = q * x1i3 + oI3 * x1r3;
        y3 = x2r * w3rb - x2i * w3ib;
    }
    __syncthreads();   // all warps done reading u.cx before overlay reuse
    u.sred[wb][4 * lane + 0] = y0;
    u.sred[wb][4 * lane + 1] = y1;
    u.sred[wb][4 * lane + 2] = y2;
    u.sred[wb][4 * lane + 3] = y3;
    __syncthreads();

    // ---- reduce 8 bands within block; publish t-major partial ----
    if (tid < TILE_T) {
        float r = 0.f;
        #pragma unroll
        for (int w = 0; w < BPB; w++) r += u.sred[w][tid];
        ((float*)&g_part[tileBase + tid][0])[blockIdx.y] = r;
    }

    // ---- fence + ticket: last block of this tile finalizes ----
    __threadfence();
    if (tid == 0)
        s_ticket = atomicAdd(&g_cnt[tile], 1);
    __syncthreads();
    if (s_ticket == NGROUPS - 1) {
        if (tid < TILE_T) {
            int t = tileBase + tid;
            float4 pa = g_part[t][0];
            float4 pb = g_part[t][1];
            out[t] = ((pa.x + pa.y) + (pa.z + pa.w)) + ((pb.x + pb.y) + (pb.z + pb.w));
        }
        if (tid == 0)
            g_cnt[tile] = 0;   // reset for next launch / graph replay
    }
}

extern "C" void kernel_launch(void* const* d_in, const int* in_sizes, int n_in,
                              void* d_out, int out_size)
{
    // Input ordering: order A (dict/signature) confirmed (in_sizes[0]==16384).
    int I_xr, I_xi, I_w1r, I_w1i, I_cr, I_ci, I_sr, I_si, I_fcr, I_fci, I_w3r, I_w3i;
    if (in_sizes[0] == T_LEN) {
        I_xr = 0;  I_xi = 1;  I_w1r = 2; I_w1i = 3; I_cr = 4;  I_ci = 5;
        I_sr = 6;  I_si = 7;  I_fcr = 8; I_fci = 9; I_w3r = 10; I_w3i = 11;
    } else {
        I_ci = 0;  I_cr = 1;  I_fci = 2; I_fcr = 3; I_si = 4;  I_sr = 5;
        I_w1i = 6; I_w1r = 7; I_w3i = 8; I_w3r = 9; I_xi = 10; I_xr = 11;
    }

    const float* x_r  = (const float*)d_in[I_xr];
    const float* x_i  = (const float*)d_in[I_xi];
    const float* w1_r = (const float*)d_in[I_w1r];
    const float* w1_i = (const float*)d_in[I_w1i];
    const float* c_r  = (const float*)d_in[I_cr];
    const float* c_i  = (const float*)d_in[I_ci];
    const float* s_r  = (const float*)d_in[I_sr];
    const float* s_i  = (const float*)d_in[I_si];
    const float* fc_r = (const float*)d_in[I_fcr];
    const float* fc_i = (const float*)d_in[I_fci];
    const float* w3_r = (const float*)d_in[I_w3r];
    const float* w3_i = (const float*)d_in[I_w3i];
    float* out = (float*)d_out;

    dim3 grid(NTILES, NGROUPS);
    fused_kernel<<<grid, THREADS>>>(x_r, x_i, w1_r, w1_i,
                                    c_r, c_i, s_r, s_i, fc_r, fc_i,
                                    w3_r, w3_i, out);
}